// round 2
// baseline (speedup 1.0000x reference)
#include <cuda_runtime.h>
#include <math.h>

#define NN   100000
#define EE   3200000
#define H    64
#define DIN  15
#define DOUT 12
#define NT   5
#define GG   256
#define STEPS 6

// ---------------- scratch (no allocation allowed; device globals) ----------
__device__ float g_out0[NN * H];                 // 25.6 MB
__device__ float g_h[NN * H];                    // 25.6 MB (out == h)
__device__ float g_m[NN * H];                    // agg -> m
__device__ float g_T[(size_t)NN * NT * H];       // 128 MB
__device__ float g_g[(size_t)NN * 6 * H];        // gx(192) | gh(192) per node
__device__ float g_t1[NN * H];
__device__ float g_t2[NN * H];
__device__ float g_deg[NN];

__device__ __forceinline__ float sigmoidf_(float v) {
    return 1.0f / (1.0f + expf(-v));
}

// ---------------- generic zero ----------------
__global__ void zero_kernel(float* __restrict__ p, int n) {
    int i = blockIdx.x * blockDim.x + threadIdx.x;
    if (i < n) p[i] = 0.0f;
}

// ---------------- lin0: out0 = relu(x @ W + b); h = out0 ----------------
__global__ void lin0_kernel(const float* __restrict__ x,
                            const float* __restrict__ w,
                            const float* __restrict__ b,
                            float* __restrict__ out0,
                            float* __restrict__ h) {
    __shared__ float sw[DIN * H];
    __shared__ float sb[H];
    __shared__ float sx[4][DIN];
    int tid = threadIdx.x;
    for (int i = tid; i < DIN * H; i += 256) sw[i] = w[i];
    if (tid < H) sb[tid] = b[tid];
    int n0 = blockIdx.x * 4;
    if (tid < 4 * DIN) {
        int ln = tid / DIN, k = tid % DIN;
        int n = n0 + ln;
        sx[ln][k] = (n < NN) ? x[n * DIN + k] : 0.0f;
    }
    __syncthreads();
    int ln = tid / H, o = tid % H;
    int n = n0 + ln;
    if (n < NN) {
        float acc = sb[o];
#pragma unroll
        for (int k = 0; k < DIN; k++) acc += sx[ln][k] * sw[k * H + o];
        acc = fmaxf(acc, 0.0f);
        out0[n * H + o] = acc;
        h[n * H + o] = acc;
    }
}

// ---------------- degree ----------------
__global__ void deg_kernel(const int* __restrict__ dst, float* __restrict__ deg) {
    int e = blockIdx.x * blockDim.x + threadIdx.x;
    if (e < EE) atomicAdd(&deg[dst[e]], 1.0f);
}

// ---------------- tiled GEMM: C[64-row blk][64-col blk] = A[M,K] @ B[K,64] --
// A row-major with row length 64 (or 64+64 concat for K=128).
// B block chosen by blockIdx.y: Bb = B + y*bStride (row stride ldb).
// C block: Cb = C + y*cStride (row stride ldc).
// EPI: 0 = none, 1 = sigmoid. bias (len 64 per col-block) optional.
template <int K, bool CONCAT, int EPI>
__global__ __launch_bounds__(256) void gemm_tile(
    const float* __restrict__ A0, const float* __restrict__ A1,
    const float* __restrict__ B, int ldb, long bStride,
    const float* __restrict__ bias,
    float* __restrict__ C, int ldc, long cStride) {
    extern __shared__ float smem[];
    float* sA = smem;            // [K][65] (transposed, padded)
    float* sB = smem + K * 65;   // [K][64]

    const int tid = threadIdx.x;
    const int m0 = blockIdx.x * 64;
    const float* Bb = B + (long)blockIdx.y * bStride;
    float* Cb = C + (long)blockIdx.y * cStride;

    constexpr int KQ = K / 4;      // float4s per A row
    // ---- load A (transpose into sA[k][m]) ----
#pragma unroll
    for (int r = 0; r < KQ / 4; r++) {
        int i = tid + 256 * r;
        int m = i / KQ, kq = i % KQ;
        int gm = m0 + m;
        float4 v = make_float4(0.f, 0.f, 0.f, 0.f);
        if (gm < NN) {
            if (!CONCAT || kq < 16)
                v = *(const float4*)(A0 + (size_t)gm * 64 + kq * 4);
            else
                v = *(const float4*)(A1 + (size_t)gm * 64 + (kq - 16) * 4);
        }
        int k = kq * 4;
        sA[(k + 0) * 65 + m] = v.x;
        sA[(k + 1) * 65 + m] = v.y;
        sA[(k + 2) * 65 + m] = v.z;
        sA[(k + 3) * 65 + m] = v.w;
    }
    // ---- load B ----
#pragma unroll
    for (int r = 0; r < K / 16; r++) {
        int i = tid + 256 * r;
        int k = i / 16, n4 = i % 16;
        float4 v = *(const float4*)(Bb + (size_t)k * ldb + n4 * 4);
        *(float4*)(sB + k * 64 + n4 * 4) = v;
    }
    __syncthreads();

    float acc[4][4];
#pragma unroll
    for (int i = 0; i < 4; i++)
#pragma unroll
        for (int j = 0; j < 4; j++) acc[i][j] = 0.0f;

    const int tx = tid % 16, ty = tid / 16;
#pragma unroll 8
    for (int k = 0; k < K; k++) {
        float a0 = sA[k * 65 + ty * 4 + 0];
        float a1 = sA[k * 65 + ty * 4 + 1];
        float a2 = sA[k * 65 + ty * 4 + 2];
        float a3 = sA[k * 65 + ty * 4 + 3];
        float4 bv = *(const float4*)(sB + k * 64 + tx * 4);
        acc[0][0] += a0 * bv.x; acc[0][1] += a0 * bv.y; acc[0][2] += a0 * bv.z; acc[0][3] += a0 * bv.w;
        acc[1][0] += a1 * bv.x; acc[1][1] += a1 * bv.y; acc[1][2] += a1 * bv.z; acc[1][3] += a1 * bv.w;
        acc[2][0] += a2 * bv.x; acc[2][1] += a2 * bv.y; acc[2][2] += a2 * bv.z; acc[2][3] += a2 * bv.w;
        acc[3][0] += a3 * bv.x; acc[3][1] += a3 * bv.y; acc[3][2] += a3 * bv.z; acc[3][3] += a3 * bv.w;
    }

#pragma unroll
    for (int i = 0; i < 4; i++) {
        int gm = m0 + ty * 4 + i;
        if (gm < NN) {
            float4 o;
            o.x = acc[i][0]; o.y = acc[i][1]; o.z = acc[i][2]; o.w = acc[i][3];
            if (bias) {
                o.x += bias[tx * 4 + 0];
                o.y += bias[tx * 4 + 1];
                o.z += bias[tx * 4 + 2];
                o.w += bias[tx * 4 + 3];
            }
            if (EPI == 1) {
                o.x = sigmoidf_(o.x); o.y = sigmoidf_(o.y);
                o.z = sigmoidf_(o.z); o.w = sigmoidf_(o.w);
            }
            *(float4*)(Cb + (size_t)gm * ldc + tx * 4) = o;
        }
    }
}

// ---------------- edge scatter: agg[dst] += T[src, type, :] ----------------
__global__ void scatter_kernel(const int* __restrict__ src,
                               const int* __restrict__ dst,
                               const int* __restrict__ et,
                               const float* __restrict__ T,
                               float* __restrict__ agg) {
    __shared__ int ss[16], sd[16], st[16];
    int e0 = blockIdx.x * 16;
    int tid = threadIdx.x;
    if (tid < 16) {
        int e = e0 + tid;
        ss[tid] = (e < EE) ? src[e] : 0;
    } else if (tid < 32) {
        int e = e0 + tid - 16;
        sd[tid - 16] = (e < EE) ? dst[e] : 0;
    } else if (tid < 48) {
        int e = e0 + tid - 32;
        st[tid - 32] = (e < EE) ? et[e] : 0;
    }
    __syncthreads();
    int el = tid >> 4;             // 0..15 edge within block
    int c = (tid & 15) << 2;       // 0..60 column chunk (float4)
    if (e0 + el < EE) {
        const float4 v = *(const float4*)(T + (size_t)ss[el] * (NT * H) + st[el] * H + c);
        float4* p = (float4*)(agg + (size_t)sd[el] * H + c);
#if __CUDA_ARCH__ >= 900
        atomicAdd(p, v);
#else
        float* q = (float*)p;
        atomicAdd(q + 0, v.x); atomicAdd(q + 1, v.y);
        atomicAdd(q + 2, v.z); atomicAdd(q + 3, v.w);
#endif
    }
}

// ---------------- m = relu(agg / max(deg,1) + conv_bias) ----------------
__global__ void mrelu_kernel(float* __restrict__ m,
                             const float* __restrict__ deg,
                             const float* __restrict__ cbias) {
    int idx = blockIdx.x * blockDim.x + threadIdx.x;
    if (idx >= NN * H) return;
    int n = idx >> 6, j = idx & 63;
    float d = fmaxf(deg[n], 1.0f);
    m[idx] = fmaxf(m[idx] / d + cbias[j], 0.0f);
}

// ---------------- GRU gates (torch order r,z,n); h updated in place -------
__global__ void gru_gate_kernel(const float* __restrict__ g,
                                float* __restrict__ h,
                                const float* __restrict__ b_ih,
                                const float* __restrict__ b_hh) {
    int idx = blockIdx.x * blockDim.x + threadIdx.x;
    if (idx >= NN * H) return;
    int n = idx >> 6, j = idx & 63;
    const float* gr = g + (size_t)n * 384;
    float xr = gr[j]        + b_ih[j];
    float xz = gr[64 + j]   + b_ih[64 + j];
    float xn = gr[128 + j]  + b_ih[128 + j];
    float hr = gr[192 + j]  + b_hh[j];
    float hz = gr[256 + j]  + b_hh[64 + j];
    float hn = gr[320 + j]  + b_hh[128 + j];
    float r = sigmoidf_(xr + hr);
    float z = sigmoidf_(xz + hz);
    float nv = tanhf(xn + r * hn);
    float hv = h[idx];
    h[idx] = (1.0f - z) * nv + z * hv;
}

// ---------------- readout: i*j then segment-sum over batch ----------------
__global__ void readout_kernel(const float* __restrict__ t1,
                               const float* __restrict__ t2,
                               const int* __restrict__ batch,
                               const float* __restrict__ i_w2,
                               const float* __restrict__ i_b2,
                               const float* __restrict__ j_w2,
                               const float* __restrict__ j_b2,
                               float* __restrict__ out) {
    __shared__ float siw[H * DOUT], sjw[H * DOUT], sib[DOUT], sjb[DOUT];
    int tid = threadIdx.x;
    for (int i = tid; i < H * DOUT; i += 256) {
        siw[i] = i_w2[i];
        sjw[i] = j_w2[i];
    }
    if (tid < DOUT) { sib[tid] = i_b2[tid]; sjb[tid] = j_b2[tid]; }
    __syncthreads();
    int n = blockIdx.x * 256 + tid;
    if (n >= NN) return;
    float ai[DOUT], aj[DOUT];
#pragma unroll
    for (int c = 0; c < DOUT; c++) { ai[c] = sib[c]; aj[c] = sjb[c]; }
    const float* r1 = t1 + (size_t)n * H;
    const float* r2 = t2 + (size_t)n * H;
#pragma unroll 4
    for (int k = 0; k < H; k++) {
        float a = r1[k], b = r2[k];
#pragma unroll
        for (int c = 0; c < DOUT; c++) {
            ai[c] += a * siw[k * DOUT + c];
            aj[c] += b * sjw[k * DOUT + c];
        }
    }
    float* ob = out + (size_t)batch[n] * DOUT;
#pragma unroll
    for (int c = 0; c < DOUT; c++) {
        float iv = sigmoidf_(ai[c]);
        atomicAdd(&ob[c], iv * aj[c]);
    }
}

// ---------------- launch ----------------
extern "C" void kernel_launch(void* const* d_in, const int* in_sizes, int n_in,
                              void* d_out, int out_size) {
    const float* x      = (const float*)d_in[0];
    const int*   ei     = (const int*)d_in[1];
    const int*   ea     = (const int*)d_in[2];
    const int*   batch  = (const int*)d_in[3];
    const float* lin0_w = (const float*)d_in[4];
    const float* lin0_b = (const float*)d_in[5];
    const float* eemb   = (const float*)d_in[6];
    const float* cbias  = (const float*)d_in[7];
    const float* w_ih   = (const float*)d_in[8];
    const float* w_hh   = (const float*)d_in[9];
    const float* b_ih   = (const float*)d_in[10];
    const float* b_hh   = (const float*)d_in[11];
    const float* i_w1   = (const float*)d_in[12];
    const float* i_b1   = (const float*)d_in[13];
    const float* i_w2   = (const float*)d_in[14];
    const float* i_b2   = (const float*)d_in[15];
    const float* j_w1   = (const float*)d_in[16];
    const float* j_b1   = (const float*)d_in[17];
    const float* j_w2   = (const float*)d_in[18];
    const float* j_b2   = (const float*)d_in[19];
    const int* src = ei;
    const int* dst = ei + EE;
    float* out = (float*)d_out;

    float *ph, *pout0, *pm, *pT, *pg, *pt1, *pt2, *pdeg;
    cudaGetSymbolAddress((void**)&ph,    g_h);
    cudaGetSymbolAddress((void**)&pout0, g_out0);
    cudaGetSymbolAddress((void**)&pm,    g_m);
    cudaGetSymbolAddress((void**)&pT,    g_T);
    cudaGetSymbolAddress((void**)&pg,    g_g);
    cudaGetSymbolAddress((void**)&pt1,   g_t1);
    cudaGetSymbolAddress((void**)&pt2,   g_t2);
    cudaGetSymbolAddress((void**)&pdeg,  g_deg);

    const int MB = (NN + 63) / 64;
    const size_t smem64  = (64 * 65 + 64 * 64) * sizeof(float);
    const size_t smem128 = (128 * 65 + 128 * 64) * sizeof(float);
    cudaFuncSetAttribute(gemm_tile<128, true, 1>,
                         cudaFuncAttributeMaxDynamicSharedMemorySize,
                         (int)smem128);

    // init
    zero_kernel<<<(NN + 255) / 256, 256>>>(pdeg, NN);
    zero_kernel<<<(GG * DOUT + 255) / 256, 256>>>(out, GG * DOUT);
    lin0_kernel<<<(NN + 3) / 4, 256>>>(x, lin0_w, lin0_b, pout0, ph);
    deg_kernel<<<(EE + 255) / 256, 256>>>(dst, pdeg);

    for (int s = 0; s < STEPS; s++) {
        zero_kernel<<<(NN * H + 255) / 256, 256>>>(pm, NN * H);
        // T[n,t,:] = h[n,:] @ W_t    (B block per type, C col-block per type)
        gemm_tile<64, false, 0><<<dim3(MB, NT), 256, smem64>>>(
            ph, nullptr, eemb, 64, (long)(H * H), nullptr, pT, NT * H, 64);
        scatter_kernel<<<EE / 16, 256>>>(src, dst, ea, pT, pm);
        mrelu_kernel<<<(NN * H + 255) / 256, 256>>>(pm, pdeg, cbias);
        // gx = m @ W_ih (cols 0..191) ; gh = h @ W_hh (cols 192..383)
        gemm_tile<64, false, 0><<<dim3(MB, 3), 256, smem64>>>(
            pm, nullptr, w_ih, 3 * H, 64, nullptr, pg, 6 * H, 64);
        gemm_tile<64, false, 0><<<dim3(MB, 3), 256, smem64>>>(
            ph, nullptr, w_hh, 3 * H, 64, nullptr, pg + 3 * H, 6 * H, 64);
        gru_gate_kernel<<<(NN * H + 255) / 256, 256>>>(pg, ph, b_ih, b_hh);
    }

    // readout
    gemm_tile<128, true, 1><<<dim3(MB, 1), 256, smem128>>>(
        ph, pout0, i_w1, 64, 0, i_b1, pt1, 64, 0);
    gemm_tile<64, false, 1><<<dim3(MB, 1), 256, smem64>>>(
        ph, nullptr, j_w1, 64, 0, j_b1, pt2, 64, 0);
    readout_kernel<<<(NN + 255) / 256, 256>>>(
        pt1, pt2, batch, i_w2, i_b2, j_w2, j_b2, out);
}

// round 4
// speedup vs baseline: 1.1018x; 1.1018x over previous
#include <cuda_runtime.h>
#include <mma.h>
#include <math.h>
#include <cstdint>

using namespace nvcuda;

#define NN   100000
#define EE   3200000
#define H    64
#define DIN  15
#define DOUT 12
#define NT   5
#define GG   256
#define STEPS 6

#define RT    32                  // rows per CTA for WMMA kernels
#define NCTA  (NN / RT)           // 3125 (exact: 100000 = 32*3125)
#define KAUG  72                  // 64 + augmented bias column + pad to mult of 8
#define PSZ   (KAUG * 64)         // floats per B panel (4608)

// ---------------- scratch (device globals; no allocation) ----------------
__device__ float g_out0[NN * H];
__device__ float g_h[NN * H];
__device__ float g_agg[NN * H];
__device__ float g_T[(size_t)NN * NT * H];     // 128 MB, row = 320 floats
__device__ float g_t1[NN * H];
__device__ float g_t2[NN * H];
__device__ float g_deg[NN];
__device__ float g_Bimg[11 * PSZ];             // panels: 0..4 T, 5..7 ih(r,z,n), 8..10 hh(r,z,n)

__device__ __forceinline__ float sigmoidf_(float v) { return 1.0f / (1.0f + expf(-v)); }

typedef wmma::fragment<wmma::matrix_a, 16, 16, 8, wmma::precision::tf32, wmma::row_major> AFrag;
typedef wmma::fragment<wmma::matrix_b, 16, 16, 8, wmma::precision::tf32, wmma::row_major> BFrag;
typedef wmma::fragment<wmma::accumulator, 16, 16, 8, float> CFrag;

#define CVT_A(f) do { _Pragma("unroll") \
    for (int _t = 0; _t < (f).num_elements; _t++) (f).x[_t] = wmma::__float_to_tf32((f).x[_t]); } while (0)

// ---------------- misc kernels ----------------
__global__ void zero_kernel(float* __restrict__ p, int n) {
    int i = blockIdx.x * blockDim.x + threadIdx.x;
    if (i < n) p[i] = 0.0f;
}

__global__ void deg_kernel(const int* __restrict__ dst, float* __restrict__ deg) {
    int e = blockIdx.x * blockDim.x + threadIdx.x;
    if (e < EE) atomicAdd(&deg[dst[e]], 1.0f);
}

// B panels, K-augmented (row k, col n), ld = 64.
// p<5:  rows 0..63 = W_t[k][n] (eemb), rows 64..71 = 0
// p5..7:  c0=(p-5)*64: rows 0..63 = w_ih[k][c0+n], row 64 = b_ih[c0+n], rest 0
// p8..10: same with w_hh / b_hh
__global__ void bprep_kernel(const float* __restrict__ eemb,
                             const float* __restrict__ w_ih,
                             const float* __restrict__ w_hh,
                             const float* __restrict__ b_ih,
                             const float* __restrict__ b_hh,
                             float* __restrict__ img) {
    int p = blockIdx.x;
    float* out = img + p * PSZ;
    for (int i = threadIdx.x; i < PSZ; i += 256) {
        int k = i >> 6, n = i & 63;
        float v = 0.0f;
        if (p < 5) {
            if (k < 64) v = eemb[p * 4096 + k * 64 + n];
        } else if (p < 8) {
            int c0 = (p - 5) * 64;
            if (k < 64) v = w_ih[k * 192 + c0 + n];
            else if (k == 64) v = b_ih[c0 + n];
        } else {
            int c0 = (p - 8) * 64;
            if (k < 64) v = w_hh[k * 192 + c0 + n];
            else if (k == 64) v = b_hh[c0 + n];
        }
        out[i] = v;
    }
}

__global__ void lin0_kernel(const float* __restrict__ x,
                            const float* __restrict__ w,
                            const float* __restrict__ b,
                            float* __restrict__ out0,
                            float* __restrict__ h) {
    __shared__ float sw[DIN * H];
    __shared__ float sb[H];
    __shared__ float sx[4][DIN];
    int tid = threadIdx.x;
    for (int i = tid; i < DIN * H; i += 256) sw[i] = w[i];
    if (tid < H) sb[tid] = b[tid];
    int n0 = blockIdx.x * 4;
    if (tid < 4 * DIN) {
        int ln = tid / DIN, k = tid % DIN;
        int n = n0 + ln;
        sx[ln][k] = (n < NN) ? x[n * DIN + k] : 0.0f;
    }
    __syncthreads();
    int ln = tid / H, o = tid % H;
    int n = n0 + ln;
    if (n < NN) {
        float acc = sb[o];
#pragma unroll
        for (int k = 0; k < DIN; k++) acc += sx[ln][k] * sw[k * H + o];
        acc = fmaxf(acc, 0.0f);
        out0[n * H + o] = acc;
        h[n * H + o] = acc;
    }
}

// ---------------- WMMA T GEMM: T[n, t*64+j] = h[n,:] @ W_t ----------------
// 256 thr = 8 warps; warp (rg, cg): rows gr0..gr0+15, coltiles {cg, cg+4, ..., cg+16}
__global__ __launch_bounds__(256) void t_gemm_kernel(const float* __restrict__ hmat,
                                                     const float* __restrict__ Bimg,
                                                     float* __restrict__ Tout) {
    int tid = threadIdx.x;
    int w = tid >> 5;
    int rg = w >> 2, cg = w & 3;
    int gr0 = blockIdx.x * RT + rg * 16;

    AFrag a[8];
#pragma unroll
    for (int kk = 0; kk < 8; kk++) {
        wmma::load_matrix_sync(a[kk], hmat + (size_t)gr0 * H + kk * 8, H);
        CVT_A(a[kk]);
    }
#pragma unroll
    for (int i = 0; i < 5; i++) {
        int ct = cg + 4 * i;               // 0..19
        int p = ct >> 2, jc = (ct & 3) * 16;
        CFrag acc;
        wmma::fill_fragment(acc, 0.0f);
#pragma unroll
        for (int kk = 0; kk < 8; kk++) {
            BFrag b;
            wmma::load_matrix_sync(b, Bimg + p * PSZ + kk * 8 * 64 + jc, 64);
            CVT_A(b);
            wmma::mma_sync(acc, a[kk], b, acc);
        }
        wmma::store_matrix_sync(Tout + (size_t)gr0 * (NT * H) + ct * 16, acc,
                                NT * H, wmma::mem_row_major);
    }
}

// ---------------- WMMA GRU GEMM + fused gates ----------------
// A0 = m = relu(agg/deg + cbias) built in smem (K-augmented with 1-column at k=64)
// A1 = h direct from gmem (+ smem aug tile for k=64..71)
// 6 accumulators per warp (xr,xz,xn from m; hr,hz,hn from h); gates fused; h in place
__global__ __launch_bounds__(256) void gru_gemm_kernel(const float* __restrict__ agg,
                                                       const float* __restrict__ deg,
                                                       const float* __restrict__ cbias,
                                                       const float* __restrict__ Bimg,
                                                       float* __restrict__ hmat) {
    __shared__ float sAm[RT * KAUG];
    __shared__ float sAug[RT * 8];
    int tid = threadIdx.x;
    int r0g = blockIdx.x * RT;

    // build m tile (fused relu(agg/deg + cbias)) + augmentation columns
    for (int i = tid; i < RT * 16; i += 256) {
        int r = i >> 4, q = i & 15;
        int gr = r0g + r;
        float4 a4 = *(const float4*)(agg + (size_t)gr * H + q * 4);
        float inv = 1.0f / fmaxf(deg[gr], 1.0f);
        float4 m4;
        m4.x = fmaxf(fmaf(a4.x, inv, cbias[q * 4 + 0]), 0.0f);
        m4.y = fmaxf(fmaf(a4.y, inv, cbias[q * 4 + 1]), 0.0f);
        m4.z = fmaxf(fmaf(a4.z, inv, cbias[q * 4 + 2]), 0.0f);
        m4.w = fmaxf(fmaf(a4.w, inv, cbias[q * 4 + 3]), 0.0f);
        *(float4*)(sAm + r * KAUG + q * 4) = m4;
    }
    if (tid < RT) {
        sAm[tid * KAUG + 64] = 1.0f;
#pragma unroll
        for (int c = 65; c < KAUG; c++) sAm[tid * KAUG + c] = 0.0f;
        sAug[tid * 8] = 1.0f;
#pragma unroll
        for (int c = 1; c < 8; c++) sAug[tid * 8 + c] = 0.0f;
    }
    __syncthreads();

    int w = tid >> 5;
    int rg = w >> 2, cg = w & 3;
    int r0 = rg * 16;
    int gr0 = r0g + r0;
    int j0 = cg * 16;

    CFrag xr, xz, xn, hr, hz, hn;
    wmma::fill_fragment(xr, 0.0f); wmma::fill_fragment(xz, 0.0f);
    wmma::fill_fragment(xn, 0.0f); wmma::fill_fragment(hr, 0.0f);
    wmma::fill_fragment(hz, 0.0f); wmma::fill_fragment(hn, 0.0f);

#pragma unroll
    for (int kk = 0; kk < 9; kk++) {
        int k0 = kk * 8;
        AFrag am, ah;
        wmma::load_matrix_sync(am, sAm + r0 * KAUG + k0, KAUG);
        if (k0 < 64) wmma::load_matrix_sync(ah, hmat + (size_t)gr0 * H + k0, H);
        else         wmma::load_matrix_sync(ah, sAug + r0 * 8, 8);
        CVT_A(am);
        CVT_A(ah);
        const float* bp = Bimg + 5 * PSZ + k0 * 64 + j0;
        BFrag b;
        wmma::load_matrix_sync(b, bp, 64);            CVT_A(b); wmma::mma_sync(xr, am, b, xr);
        wmma::load_matrix_sync(b, bp + PSZ, 64);      CVT_A(b); wmma::mma_sync(xz, am, b, xz);
        wmma::load_matrix_sync(b, bp + 2 * PSZ, 64);  CVT_A(b); wmma::mma_sync(xn, am, b, xn);
        wmma::load_matrix_sync(b, bp + 3 * PSZ, 64);  CVT_A(b); wmma::mma_sync(hr, ah, b, hr);
        wmma::load_matrix_sync(b, bp + 4 * PSZ, 64);  CVT_A(b); wmma::mma_sync(hz, ah, b, hz);
        wmma::load_matrix_sync(b, bp + 5 * PSZ, 64);  CVT_A(b); wmma::mma_sync(hn, ah, b, hn);
    }

    CFrag hold;
    wmma::load_matrix_sync(hold, hmat + (size_t)gr0 * H + j0, H, wmma::mem_row_major);
    __syncthreads();   // all reads of hmat done before any warp stores

#pragma unroll
    for (int t = 0; t < hold.num_elements; t++) {
        float r = sigmoidf_(xr.x[t] + hr.x[t]);
        float z = sigmoidf_(xz.x[t] + hz.x[t]);
        float nv = tanhf(xn.x[t] + r * hn.x[t]);
        hold.x[t] = (1.0f - z) * nv + z * hold.x[t];
    }
    wmma::store_matrix_sync(hmat + (size_t)gr0 * H + j0, hold, H, wmma::mem_row_major);
}

// ---------------- edge scatter: agg[dst] += T[src, type, :] ----------------
__global__ void scatter_kernel(const int* __restrict__ src,
                               const int* __restrict__ dst,
                               const int* __restrict__ et,
                               const float* __restrict__ T,
                               float* __restrict__ agg) {
    __shared__ int ss[16], sd[16], st[16];
    int e0 = blockIdx.x * 16;
    int tid = threadIdx.x;
    if (tid < 16) {
        int e = e0 + tid;
        ss[tid] = (e < EE) ? src[e] : 0;
    } else if (tid < 32) {
        int e = e0 + tid - 16;
        sd[tid - 16] = (e < EE) ? dst[e] : 0;
    } else if (tid < 48) {
        int e = e0 + tid - 32;
        st[tid - 32] = (e < EE) ? et[e] : 0;
    }
    __syncthreads();
    int el = tid >> 4;
    int c = (tid & 15) << 2;
    if (e0 + el < EE) {
        const float4 v = *(const float4*)(T + (size_t)ss[el] * (NT * H) + st[el] * H + c);
        float4* p = (float4*)(agg + (size_t)sd[el] * H + c);
        atomicAdd(p, v);
    }
}

// ---------------- readout (SIMT, runs once) ----------------
template <int K, bool CONCAT, int EPI>
__global__ __launch_bounds__(256) void gemm_tile(
    const float* __restrict__ A0, const float* __restrict__ A1,
    const float* __restrict__ B, int ldb, long bStride,
    const float* __restrict__ bias,
    float* __restrict__ C, int ldc, long cStride) {
    extern __shared__ float fsm[];
    float* sA = fsm;
    float* sB = fsm + K * 65;
    const int tid = threadIdx.x;
    const int m0 = blockIdx.x * 64;
    const float* Bb = B + (long)blockIdx.y * bStride;
    float* Cb = C + (long)blockIdx.y * cStride;
    constexpr int KQ = K / 4;
#pragma unroll
    for (int r = 0; r < KQ / 4; r++) {
        int i = tid + 256 * r;
        int m = i / KQ, kq = i % KQ;
        int gm = m0 + m;
        float4 v = make_float4(0.f, 0.f, 0.f, 0.f);
        if (gm < NN) {
            if (!CONCAT || kq < 16) v = *(const float4*)(A0 + (size_t)gm * 64 + kq * 4);
            else v = *(const float4*)(A1 + (size_t)gm * 64 + (kq - 16) * 4);
        }
        int k = kq * 4;
        sA[(k + 0) * 65 + m] = v.x; sA[(k + 1) * 65 + m] = v.y;
        sA[(k + 2) * 65 + m] = v.z; sA[(k + 3) * 65 + m] = v.w;
    }
#pragma unroll
    for (int r = 0; r < K / 16; r++) {
        int i = tid + 256 * r;
        int k = i / 16, n4 = i % 16;
        float4 v = *(const float4*)(Bb + (size_t)k * ldb + n4 * 4);
        *(float4*)(sB + k * 64 + n4 * 4) = v;
    }
    __syncthreads();
    float acc[4][4];
#pragma unroll
    for (int i = 0; i < 4; i++)
#pragma unroll
        for (int j = 0; j < 4; j++) acc[i][j] = 0.0f;
    const int tx = tid % 16, ty = tid / 16;
#pragma unroll 8
    for (int k = 0; k < K; k++) {
        float a0 = sA[k * 65 + ty * 4 + 0];
        float a1 = sA[k * 65 + ty * 4 + 1];
        float a2 = sA[k * 65 + ty * 4 + 2];
        float a3 = sA[k * 65 + ty * 4 + 3];
        float4 bv = *(const float4*)(sB + k * 64 + tx * 4);
        acc[0][0] += a0 * bv.x; acc[0][1] += a0 * bv.y; acc[0][2] += a0 * bv.z; acc[0][3] += a0 * bv.w;
        acc[1][0] += a1 * bv.x; acc[1][1] += a1 * bv.y; acc[1][2] += a1 * bv.z; acc[1][3] += a1 * bv.w;
        acc[2][0] += a2 * bv.x; acc[2][1] += a2 * bv.y; acc[2][2] += a2 * bv.z; acc[2][3] += a2 * bv.w;
        acc[3][0] += a3 * bv.x; acc[3][1] += a3 * bv.y; acc[3][2] += a3 * bv.z; acc[3][3] += a3 * bv.w;
    }
#pragma unroll
    for (int i = 0; i < 4; i++) {
        int gm = m0 + ty * 4 + i;
        if (gm < NN) {
            float4 o;
            o.x = acc[i][0]; o.y = acc[i][1]; o.z = acc[i][2]; o.w = acc[i][3];
            if (bias) {
                o.x += bias[tx * 4 + 0]; o.y += bias[tx * 4 + 1];
                o.z += bias[tx * 4 + 2]; o.w += bias[tx * 4 + 3];
            }
            if (EPI == 1) {
                o.x = sigmoidf_(o.x); o.y = sigmoidf_(o.y);
                o.z = sigmoidf_(o.z); o.w = sigmoidf_(o.w);
            }
            *(float4*)(Cb + (size_t)gm * ldc + tx * 4) = o;
        }
    }
}

__global__ void readout_kernel(const float* __restrict__ t1,
                               const float* __restrict__ t2,
                               const int* __restrict__ batch,
                               const float* __restrict__ i_w2,
                               const float* __restrict__ i_b2,
                               const float* __restrict__ j_w2,
                               const float* __restrict__ j_b2,
                               float* __restrict__ out) {
    __shared__ float siw[H * DOUT], sjw[H * DOUT], sib[DOUT], sjb[DOUT];
    int tid = threadIdx.x;
    for (int i = tid; i < H * DOUT; i += 256) { siw[i] = i_w2[i]; sjw[i] = j_w2[i]; }
    if (tid < DOUT) { sib[tid] = i_b2[tid]; sjb[tid] = j_b2[tid]; }
    __syncthreads();
    int n = blockIdx.x * 256 + tid;
    if (n >= NN) return;
    float ai[DOUT], aj[DOUT];
#pragma unroll
    for (int c = 0; c < DOUT; c++) { ai[c] = sib[c]; aj[c] = sjb[c]; }
    const float* r1 = t1 + (size_t)n * H;
    const float* r2 = t2 + (size_t)n * H;
#pragma unroll 4
    for (int k = 0; k < H; k++) {
        float a = r1[k], b = r2[k];
#pragma unroll
        for (int c = 0; c < DOUT; c++) {
            ai[c] += a * siw[k * DOUT + c];
            aj[c] += b * sjw[k * DOUT + c];
        }
    }
    float* ob = out + (size_t)batch[n] * DOUT;
#pragma unroll
    for (int c = 0; c < DOUT; c++) {
        float iv = sigmoidf_(ai[c]);
        atomicAdd(&ob[c], iv * aj[c]);
    }
}

// ---------------- launch ----------------
extern "C" void kernel_launch(void* const* d_in, const int* in_sizes, int n_in,
                              void* d_out, int out_size) {
    const float* x      = (const float*)d_in[0];
    const int*   ei     = (const int*)d_in[1];
    const int*   ea     = (const int*)d_in[2];
    const int*   batch  = (const int*)d_in[3];
    const float* lin0_w = (const float*)d_in[4];
    const float* lin0_b = (const float*)d_in[5];
    const float* eemb   = (const float*)d_in[6];
    const float* cbias  = (const float*)d_in[7];
    const float* w_ih   = (const float*)d_in[8];
    const float* w_hh   = (const float*)d_in[9];
    const float* b_ih   = (const float*)d_in[10];
    const float* b_hh   = (const float*)d_in[11];
    const float* i_w1   = (const float*)d_in[12];
    const float* i_b1   = (const float*)d_in[13];
    const float* i_w2   = (const float*)d_in[14];
    const float* i_b2   = (const float*)d_in[15];
    const float* j_w1   = (const float*)d_in[16];
    const float* j_b1   = (const float*)d_in[17];
    const float* j_w2   = (const float*)d_in[18];
    const float* j_b2   = (const float*)d_in[19];
    const int* src = ei;
    const int* dst = ei + EE;
    float* out = (float*)d_out;

    float *ph, *pout0, *pagg, *pT, *pt1, *pt2, *pdeg, *pBimg;
    cudaGetSymbolAddress((void**)&ph,    g_h);
    cudaGetSymbolAddress((void**)&pout0, g_out0);
    cudaGetSymbolAddress((void**)&pagg,  g_agg);
    cudaGetSymbolAddress((void**)&pT,    g_T);
    cudaGetSymbolAddress((void**)&pt1,   g_t1);
    cudaGetSymbolAddress((void**)&pt2,   g_t2);
    cudaGetSymbolAddress((void**)&pdeg,  g_deg);
    cudaGetSymbolAddress((void**)&pBimg, g_Bimg);

    const size_t smem64  = (64 * 65 + 64 * 64) * sizeof(float);
    const size_t smem128 = (128 * 65 + 128 * 64) * sizeof(float);
    cudaFuncSetAttribute(gemm_tile<128, true, 1>,
                         cudaFuncAttributeMaxDynamicSharedMemorySize, (int)smem128);

    bprep_kernel<<<11, 256>>>(eemb, w_ih, w_hh, b_ih, b_hh, pBimg);
    zero_kernel<<<(NN + 255) / 256, 256>>>(pdeg, NN);
    zero_kernel<<<(GG * DOUT + 255) / 256, 256>>>(out, GG * DOUT);
    lin0_kernel<<<(NN + 3) / 4, 256>>>(x, lin0_w, lin0_b, pout0, ph);
    deg_kernel<<<(EE + 255) / 256, 256>>>(dst, pdeg);

    const int MB = (NN + 63) / 64;
    for (int s = 0; s < STEPS; s++) {
        zero_kernel<<<(NN * H + 255) / 256, 256>>>(pagg, NN * H);
        t_gemm_kernel<<<NCTA, 256>>>(ph, pBimg, pT);
        scatter_kernel<<<EE / 16, 256>>>(src, dst, ea, pT, pagg);
        gru_gemm_kernel<<<NCTA, 256>>>(pagg, pdeg, cbias, pBimg, ph);
    }

    gemm_tile<128, true, 1><<<dim3(MB, 1), 256, smem128>>>(
        ph, pout0, i_w1, 64, 0, i_b1, pt1, 64, 0);
    gemm_tile<64, false, 1><<<dim3(MB, 1), 256, smem64>>>(
        ph, nullptr, j_w1, 64, 0, j_b1, pt2, 64, 0);
    readout_kernel<<<(NN + 255) / 256, 256>>>(
        pt1, pt2, batch, i_w2, i_b2, j_w2, j_b2, out);
}

// round 5
// speedup vs baseline: 1.3741x; 1.2472x over previous
#include <cuda_runtime.h>
#include <mma.h>
#include <math.h>
#include <cstdint>

using namespace nvcuda;

#define NN   100000
#define EE   3200000
#define H    64
#define DIN  15
#define DOUT 12
#define NT   5
#define GG   256
#define STEPS 6

#define RT    32                  // rows per CTA for the GRU WMMA kernel
#define NCTA  (NN / RT)           // 3125
#define KAUG  72                  // 64 + bias-augmentation column, padded to x8
#define PSZ   (KAUG * 64)         // floats per augmented B panel

#define CNTPAD 100096             // 391 * 256
#define NCHUNK 391

// ---------------- scratch (device globals; no allocation) ----------------
__device__ float g_out0[NN * H];
__device__ float g_h[NN * H];
__device__ float g_S[(size_t)NN * NT * H];     // 128 MB: S[n][t][64]
__device__ float g_t1[NN * H];
__device__ float g_t2[NN * H];
__device__ float g_Bimg[6 * PSZ];              // aug panels: ih r,z,n ; hh r,z,n
__device__ int   g_cnt[CNTPAD];
__device__ int   g_off[NN + 1];
__device__ int   g_cursor[NN];
__device__ int   g_packed[EE];
__device__ int   g_psum[512];
__device__ int   g_pref[512];

__device__ __forceinline__ float sigmoidf_(float v) { return 1.0f / (1.0f + expf(-v)); }

typedef wmma::fragment<wmma::matrix_a, 16, 16, 8, wmma::precision::tf32, wmma::row_major> AFrag;
typedef wmma::fragment<wmma::matrix_b, 16, 16, 8, wmma::precision::tf32, wmma::row_major> BFrag;
typedef wmma::fragment<wmma::accumulator, 16, 16, 8, float> CFrag;

#define CVT_A(f) do { _Pragma("unroll") \
    for (int _t = 0; _t < (f).num_elements; _t++) (f).x[_t] = wmma::__float_to_tf32((f).x[_t]); } while (0)

// ---------------- misc ----------------
__global__ void zeroi_kernel(int* __restrict__ p, int n) {
    int i = blockIdx.x * blockDim.x + threadIdx.x;
    if (i < n) p[i] = 0;
}
__global__ void zerof_kernel(float* __restrict__ p, int n) {
    int i = blockIdx.x * blockDim.x + threadIdx.x;
    if (i < n) p[i] = 0.0f;
}

// ---------------- edge sort by dst (counting sort) ----------------
__global__ void hist_kernel(const int* __restrict__ dst, int* __restrict__ cnt) {
    int e = blockIdx.x * blockDim.x + threadIdx.x;
    if (e < EE) atomicAdd(&cnt[dst[e]], 1);
}
__global__ void chunksum_kernel(const int* __restrict__ cnt, int* __restrict__ psum) {
    __shared__ int s[256];
    int t = threadIdx.x;
    s[t] = cnt[blockIdx.x * 256 + t];
    __syncthreads();
#pragma unroll
    for (int d = 128; d > 0; d >>= 1) {
        if (t < d) s[t] += s[t + d];
        __syncthreads();
    }
    if (t == 0) psum[blockIdx.x] = s[0];
}
__global__ void scan_kernel(const int* __restrict__ psum, int* __restrict__ pref) {
    __shared__ int s[512];
    int t = threadIdx.x;
    int v = (t < NCHUNK) ? psum[t] : 0;
    s[t] = v;
    __syncthreads();
#pragma unroll
    for (int d = 1; d < 512; d <<= 1) {
        int x = (t >= d) ? s[t - d] : 0;
        __syncthreads();
        s[t] += x;
        __syncthreads();
    }
    if (t < NCHUNK) pref[t] = s[t] - v;   // exclusive
}
__global__ void offs_kernel(const int* __restrict__ cnt, const int* __restrict__ pref,
                            int* __restrict__ off, int* __restrict__ cursor) {
    __shared__ int s[256];
    int t = threadIdx.x;
    int gid = blockIdx.x * 256 + t;
    int v = cnt[gid];
    s[t] = v;
    __syncthreads();
#pragma unroll
    for (int d = 1; d < 256; d <<= 1) {
        int x = (t >= d) ? s[t - d] : 0;
        __syncthreads();
        s[t] += x;
        __syncthreads();
    }
    int excl = s[t] - v + pref[blockIdx.x];
    if (gid <= NN) {
        off[gid] = excl;
        if (gid < NN) cursor[gid] = excl;
    }
}
__global__ void place_kernel(const int* __restrict__ src, const int* __restrict__ dst,
                             const int* __restrict__ et, int* __restrict__ cursor,
                             int* __restrict__ packed) {
    int e = blockIdx.x * blockDim.x + threadIdx.x;
    if (e < EE) {
        int pos = atomicAdd(&cursor[dst[e]], 1);
        packed[pos] = src[e] | (et[e] << 20);
    }
}

// ---------------- B panel prep (augmented GRU weights only) ----------------
// panel p (0..2): w_ih cols [p*64,(p+1)*64), row64 = b_ih ; p (3..5): w_hh / b_hh
__global__ void bprep_kernel(const float* __restrict__ w_ih,
                             const float* __restrict__ w_hh,
                             const float* __restrict__ b_ih,
                             const float* __restrict__ b_hh,
                             float* __restrict__ img) {
    int p = blockIdx.x;
    float* out = img + p * PSZ;
    const float* W = (p < 3) ? w_ih : w_hh;
    const float* B = (p < 3) ? b_ih : b_hh;
    int c0 = (p % 3) * 64;
    for (int i = threadIdx.x; i < PSZ; i += 256) {
        int k = i >> 6, n = i & 63;
        float v = 0.0f;
        if (k < 64) v = W[k * 192 + c0 + n];
        else if (k == 64) v = B[c0 + n];
        out[i] = v;
    }
}

__global__ void lin0_kernel(const float* __restrict__ x,
                            const float* __restrict__ w,
                            const float* __restrict__ b,
                            float* __restrict__ out0,
                            float* __restrict__ h) {
    __shared__ float sw[DIN * H];
    __shared__ float sb[H];
    __shared__ float sx[4][DIN];
    int tid = threadIdx.x;
    for (int i = tid; i < DIN * H; i += 256) sw[i] = w[i];
    if (tid < H) sb[tid] = b[tid];
    int n0 = blockIdx.x * 4;
    if (tid < 4 * DIN) {
        int ln = tid / DIN, k = tid % DIN;
        int n = n0 + ln;
        sx[ln][k] = (n < NN) ? x[n * DIN + k] : 0.0f;
    }
    __syncthreads();
    int ln = tid / H, o = tid % H;
    int n = n0 + ln;
    if (n < NN) {
        float acc = sb[o];
#pragma unroll
        for (int k = 0; k < DIN; k++) acc += sx[ln][k] * sw[k * H + o];
        acc = fmaxf(acc, 0.0f);
        out0[n * H + o] = acc;
        h[n * H + o] = acc;
    }
}

// ---------------- S accumulation: S[n][t][:] = sum_{e in seg(n), type t} h[src_e] ----
// warp per dst node; register float2 accumulators; no atomics.
__global__ __launch_bounds__(256) void s_accum_kernel(const float* __restrict__ h,
                                                      const int* __restrict__ packed,
                                                      const int* __restrict__ off,
                                                      float* __restrict__ S) {
    int node = blockIdx.x * 8 + (threadIdx.x >> 5);
    if (node >= NN) return;
    int lid = threadIdx.x & 31;
    int e0 = off[node], e1 = off[node + 1];

    float2 a0 = {0.f, 0.f}, a1 = {0.f, 0.f}, a2 = {0.f, 0.f},
           a3 = {0.f, 0.f}, a4 = {0.f, 0.f};

    for (int base = e0; base < e1; base += 32) {
        int pk = (base + lid < e1) ? packed[base + lid] : 0;
        int cnt = min(32, e1 - base);
        for (int j = 0; j < cnt; j++) {
            int p = __shfl_sync(0xffffffff, pk, j);
            int srcn = p & 0xFFFFF;
            int ty = p >> 20;
            float2 v = *(const float2*)(h + (size_t)srcn * H + lid * 2);
            if (ty == 0)      { a0.x += v.x; a0.y += v.y; }
            else if (ty == 1) { a1.x += v.x; a1.y += v.y; }
            else if (ty == 2) { a2.x += v.x; a2.y += v.y; }
            else if (ty == 3) { a3.x += v.x; a3.y += v.y; }
            else              { a4.x += v.x; a4.y += v.y; }
        }
    }
    float* Srow = S + (size_t)node * (NT * H) + lid * 2;
    *(float2*)(Srow + 0 * H) = a0;
    *(float2*)(Srow + 1 * H) = a1;
    *(float2*)(Srow + 2 * H) = a2;
    *(float2*)(Srow + 3 * H) = a3;
    *(float2*)(Srow + 4 * H) = a4;
}

// ---------------- fused conv-GEMM + GRU GEMM + gates ----------------
// stage1: macc[32,64] = S_rows[32,320] @ eemb(=Wstack)[320,64]
//         m = relu(macc/deg + cbias) -> smem (K-augmented)
// stage2: gx = m@Wih(+b), gh = h@Whh(+b) via 6 accum frags; gates fused; h in place
__global__ __launch_bounds__(256) void gru_gemm_kernel(const float* __restrict__ S,
                                                       const float* __restrict__ eemb,
                                                       const int* __restrict__ off,
                                                       const float* __restrict__ cbias,
                                                       const float* __restrict__ Bimg,
                                                       float* __restrict__ hmat) {
    __shared__ float sAm[RT * KAUG];
    __shared__ float sAug[RT * 8];
    __shared__ float sInvd[RT];
    int tid = threadIdx.x;
    int r0g = blockIdx.x * RT;

    int w = tid >> 5;
    int rg = w >> 2, cg = w & 3;
    int r0 = rg * 16;
    int gr0 = r0g + r0;
    int j0 = cg * 16;

    if (tid < RT) {
        int d = off[r0g + tid + 1] - off[r0g + tid];
        sInvd[tid] = 1.0f / (float)max(d, 1);
        sAug[tid * 8] = 1.0f;
#pragma unroll
        for (int c = 1; c < 8; c++) sAug[tid * 8 + c] = 0.0f;
    }

    // ---- stage 1: conv GEMM, K = 320 ----
    CFrag macc;
    wmma::fill_fragment(macc, 0.0f);
#pragma unroll
    for (int kk = 0; kk < 40; kk++) {
        AFrag a;
        wmma::load_matrix_sync(a, S + (size_t)gr0 * (NT * H) + kk * 8, NT * H);
        CVT_A(a);
        BFrag b;
        wmma::load_matrix_sync(b, eemb + kk * 8 * 64 + j0, 64);
        CVT_A(b);
        wmma::mma_sync(macc, a, b, macc);
    }
    wmma::store_matrix_sync(sAm + r0 * KAUG + j0, macc, KAUG, wmma::mem_row_major);
    __syncthreads();

    // elementwise: m = relu(macc * invdeg + cbias), plus augmentation cols
    for (int i = tid; i < RT * H; i += 256) {
        int r = i >> 6, c = i & 63;
        float v = sAm[r * KAUG + c];
        sAm[r * KAUG + c] = fmaxf(fmaf(v, sInvd[r], cbias[c]), 0.0f);
    }
    for (int i = tid; i < RT * 8; i += 256) {
        int r = i >> 3, c = i & 7;
        sAm[r * KAUG + 64 + c] = (c == 0) ? 1.0f : 0.0f;
    }
    __syncthreads();

    // ---- stage 2: GRU GEMMs ----
    CFrag xr, xz, xn, hr, hz, hn;
    wmma::fill_fragment(xr, 0.0f); wmma::fill_fragment(xz, 0.0f);
    wmma::fill_fragment(xn, 0.0f); wmma::fill_fragment(hr, 0.0f);
    wmma::fill_fragment(hz, 0.0f); wmma::fill_fragment(hn, 0.0f);

#pragma unroll
    for (int kk = 0; kk < 9; kk++) {
        int k0 = kk * 8;
        AFrag am, ah;
        wmma::load_matrix_sync(am, sAm + r0 * KAUG + k0, KAUG);
        if (k0 < 64) wmma::load_matrix_sync(ah, hmat + (size_t)gr0 * H + k0, H);
        else         wmma::load_matrix_sync(ah, sAug + r0 * 8, 8);
        CVT_A(am);
        CVT_A(ah);
        const float* bp = Bimg + k0 * 64 + j0;
        BFrag b;
        wmma::load_matrix_sync(b, bp, 64);            CVT_A(b); wmma::mma_sync(xr, am, b, xr);
        wmma::load_matrix_sync(b, bp + PSZ, 64);      CVT_A(b); wmma::mma_sync(xz, am, b, xz);
        wmma::load_matrix_sync(b, bp + 2 * PSZ, 64);  CVT_A(b); wmma::mma_sync(xn, am, b, xn);
        wmma::load_matrix_sync(b, bp + 3 * PSZ, 64);  CVT_A(b); wmma::mma_sync(hr, ah, b, hr);
        wmma::load_matrix_sync(b, bp + 4 * PSZ, 64);  CVT_A(b); wmma::mma_sync(hz, ah, b, hz);
        wmma::load_matrix_sync(b, bp + 5 * PSZ, 64);  CVT_A(b); wmma::mma_sync(hn, ah, b, hn);
    }

    CFrag hold;
    wmma::load_matrix_sync(hold, hmat + (size_t)gr0 * H + j0, H, wmma::mem_row_major);
    __syncthreads();   // all reads of hmat complete before any store

#pragma unroll
    for (int t = 0; t < hold.num_elements; t++) {
        float r = sigmoidf_(xr.x[t] + hr.x[t]);
        float z = sigmoidf_(xz.x[t] + hz.x[t]);
        float nv = tanhf(xn.x[t] + r * hn.x[t]);
        hold.x[t] = (1.0f - z) * nv + z * hold.x[t];
    }
    wmma::store_matrix_sync(hmat + (size_t)gr0 * H + j0, hold, H, wmma::mem_row_major);
}

// ---------------- readout ----------------
template <int K, bool CONCAT, int EPI>
__global__ __launch_bounds__(256) void gemm_tile(
    const float* __restrict__ A0, const float* __restrict__ A1,
    const float* __restrict__ B, int ldb, long bStride,
    const float* __restrict__ bias,
    float* __restrict__ C, int ldc, long cStride) {
    extern __shared__ float fsm[];
    float* sA = fsm;
    float* sB = fsm + K * 65;
    const int tid = threadIdx.x;
    const int m0 = blockIdx.x * 64;
    const float* Bb = B + (long)blockIdx.y * bStride;
    float* Cb = C + (long)blockIdx.y * cStride;
    constexpr int KQ = K / 4;
#pragma unroll
    for (int r = 0; r < KQ / 4; r++) {
        int i = tid + 256 * r;
        int m = i / KQ, kq = i % KQ;
        int gm = m0 + m;
        float4 v = make_float4(0.f, 0.f, 0.f, 0.f);
        if (gm < NN) {
            if (!CONCAT || kq < 16) v = *(const float4*)(A0 + (size_t)gm * 64 + kq * 4);
            else v = *(const float4*)(A1 + (size_t)gm * 64 + (kq - 16) * 4);
        }
        int k = kq * 4;
        sA[(k + 0) * 65 + m] = v.x; sA[(k + 1) * 65 + m] = v.y;
        sA[(k + 2) * 65 + m] = v.z; sA[(k + 3) * 65 + m] = v.w;
    }
#pragma unroll
    for (int r = 0; r < K / 16; r++) {
        int i = tid + 256 * r;
        int k = i / 16, n4 = i % 16;
        float4 v = *(const float4*)(Bb + (size_t)k * ldb + n4 * 4);
        *(float4*)(sB + k * 64 + n4 * 4) = v;
    }
    __syncthreads();
    float acc[4][4];
#pragma unroll
    for (int i = 0; i < 4; i++)
#pragma unroll
        for (int j = 0; j < 4; j++) acc[i][j] = 0.0f;
    const int tx = tid % 16, ty = tid / 16;
#pragma unroll 8
    for (int k = 0; k < K; k++) {
        float a0 = sA[k * 65 + ty * 4 + 0];
        float a1 = sA[k * 65 + ty * 4 + 1];
        float a2 = sA[k * 65 + ty * 4 + 2];
        float a3 = sA[k * 65 + ty * 4 + 3];
        float4 bv = *(const float4*)(sB + k * 64 + tx * 4);
        acc[0][0] += a0 * bv.x; acc[0][1] += a0 * bv.y; acc[0][2] += a0 * bv.z; acc[0][3] += a0 * bv.w;
        acc[1][0] += a1 * bv.x; acc[1][1] += a1 * bv.y; acc[1][2] += a1 * bv.z; acc[1][3] += a1 * bv.w;
        acc[2][0] += a2 * bv.x; acc[2][1] += a2 * bv.y; acc[2][2] += a2 * bv.z; acc[2][3] += a2 * bv.w;
        acc[3][0] += a3 * bv.x; acc[3][1] += a3 * bv.y; acc[3][2] += a3 * bv.z; acc[3][3] += a3 * bv.w;
    }
#pragma unroll
    for (int i = 0; i < 4; i++) {
        int gm = m0 + ty * 4 + i;
        if (gm < NN) {
            float4 o;
            o.x = acc[i][0]; o.y = acc[i][1]; o.z = acc[i][2]; o.w = acc[i][3];
            if (bias) {
                o.x += bias[tx * 4 + 0]; o.y += bias[tx * 4 + 1];
                o.z += bias[tx * 4 + 2]; o.w += bias[tx * 4 + 3];
            }
            if (EPI == 1) {
                o.x = sigmoidf_(o.x); o.y = sigmoidf_(o.y);
                o.z = sigmoidf_(o.z); o.w = sigmoidf_(o.w);
            }
            *(float4*)(Cb + (size_t)gm * ldc + tx * 4) = o;
        }
    }
}

__global__ void readout_kernel(const float* __restrict__ t1,
                               const float* __restrict__ t2,
                               const int* __restrict__ batch,
                               const float* __restrict__ i_w2,
                               const float* __restrict__ i_b2,
                               const float* __restrict__ j_w2,
                               const float* __restrict__ j_b2,
                               float* __restrict__ out) {
    __shared__ float siw[H * DOUT], sjw[H * DOUT], sib[DOUT], sjb[DOUT];
    int tid = threadIdx.x;
    for (int i = tid; i < H * DOUT; i += 256) { siw[i] = i_w2[i]; sjw[i] = j_w2[i]; }
    if (tid < DOUT) { sib[tid] = i_b2[tid]; sjb[tid] = j_b2[tid]; }
    __syncthreads();
    int n = blockIdx.x * 256 + tid;
    if (n >= NN) return;
    float ai[DOUT], aj[DOUT];
#pragma unroll
    for (int c = 0; c < DOUT; c++) { ai[c] = sib[c]; aj[c] = sjb[c]; }
    const float* r1 = t1 + (size_t)n * H;
    const float* r2 = t2 + (size_t)n * H;
#pragma unroll 4
    for (int k = 0; k < H; k++) {
        float a = r1[k], b = r2[k];
#pragma unroll
        for (int c = 0; c < DOUT; c++) {
            ai[c] += a * siw[k * DOUT + c];
            aj[c] += b * sjw[k * DOUT + c];
        }
    }
    float* ob = out + (size_t)batch[n] * DOUT;
#pragma unroll
    for (int c = 0; c < DOUT; c++) {
        float iv = sigmoidf_(ai[c]);
        atomicAdd(&ob[c], iv * aj[c]);
    }
}

// ---------------- launch ----------------
extern "C" void kernel_launch(void* const* d_in, const int* in_sizes, int n_in,
                              void* d_out, int out_size) {
    const float* x      = (const float*)d_in[0];
    const int*   ei     = (const int*)d_in[1];
    const int*   ea     = (const int*)d_in[2];
    const int*   batch  = (const int*)d_in[3];
    const float* lin0_w = (const float*)d_in[4];
    const float* lin0_b = (const float*)d_in[5];
    const float* eemb   = (const float*)d_in[6];
    const float* cbias  = (const float*)d_in[7];
    const float* w_ih   = (const float*)d_in[8];
    const float* w_hh   = (const float*)d_in[9];
    const float* b_ih   = (const float*)d_in[10];
    const float* b_hh   = (const float*)d_in[11];
    const float* i_w1   = (const float*)d_in[12];
    const float* i_b1   = (const float*)d_in[13];
    const float* i_w2   = (const float*)d_in[14];
    const float* i_b2   = (const float*)d_in[15];
    const float* j_w1   = (const float*)d_in[16];
    const float* j_b1   = (const float*)d_in[17];
    const float* j_w2   = (const float*)d_in[18];
    const float* j_b2   = (const float*)d_in[19];
    const int* src = ei;
    const int* dst = ei + EE;
    float* out = (float*)d_out;

    float *ph, *pout0, *pS, *pt1, *pt2, *pBimg;
    int *pcnt, *poff, *pcur, *ppk, *ppsum, *ppref;
    cudaGetSymbolAddress((void**)&ph,    g_h);
    cudaGetSymbolAddress((void**)&pout0, g_out0);
    cudaGetSymbolAddress((void**)&pS,    g_S);
    cudaGetSymbolAddress((void**)&pt1,   g_t1);
    cudaGetSymbolAddress((void**)&pt2,   g_t2);
    cudaGetSymbolAddress((void**)&pBimg, g_Bimg);
    cudaGetSymbolAddress((void**)&pcnt,  g_cnt);
    cudaGetSymbolAddress((void**)&poff,  g_off);
    cudaGetSymbolAddress((void**)&pcur,  g_cursor);
    cudaGetSymbolAddress((void**)&ppk,   g_packed);
    cudaGetSymbolAddress((void**)&ppsum, g_psum);
    cudaGetSymbolAddress((void**)&ppref, g_pref);

    const size_t smem64  = (64 * 65 + 64 * 64) * sizeof(float);
    const size_t smem128 = (128 * 65 + 128 * 64) * sizeof(float);
    cudaFuncSetAttribute(gemm_tile<128, true, 1>,
                         cudaFuncAttributeMaxDynamicSharedMemorySize, (int)smem128);

    // ---- once-per-call preprocessing ----
    bprep_kernel<<<6, 256>>>(w_ih, w_hh, b_ih, b_hh, pBimg);
    zeroi_kernel<<<(CNTPAD + 255) / 256, 256>>>(pcnt, CNTPAD);
    zerof_kernel<<<(GG * DOUT + 255) / 256, 256>>>(out, GG * DOUT);
    lin0_kernel<<<(NN + 3) / 4, 256>>>(x, lin0_w, lin0_b, pout0, ph);
    hist_kernel<<<(EE + 255) / 256, 256>>>(dst, pcnt);
    chunksum_kernel<<<NCHUNK, 256>>>(pcnt, ppsum);
    scan_kernel<<<1, 512>>>(ppsum, ppref);
    offs_kernel<<<NCHUNK, 256>>>(pcnt, ppref, poff, pcur);
    place_kernel<<<(EE + 255) / 256, 256>>>(src, dst, ea, pcur, ppk);

    // ---- propagation steps ----
    for (int s = 0; s < STEPS; s++) {
        s_accum_kernel<<<(NN + 7) / 8, 256>>>(ph, ppk, poff, pS);
        gru_gemm_kernel<<<NCTA, 256>>>(pS, eemb, poff, cbias, pBimg, ph);
    }

    // ---- readout ----
    const int MB = (NN + 63) / 64;
    gemm_tile<128, true, 1><<<dim3(MB, 1), 256, smem128>>>(
        ph, pout0, i_w1, 64, 0, i_b1, pt1, 64, 0);
    gemm_tile<64, false, 1><<<dim3(MB, 1), 256, smem64>>>(
        ph, nullptr, j_w1, 64, 0, j_b1, pt2, 64, 0);
    readout_kernel<<<(NN + 255) / 256, 256>>>(
        pt1, pt2, batch, i_w2, i_b2, j_w2, j_b2, out);
}